// round 1
// baseline (speedup 1.0000x reference)
#include <cuda_runtime.h>

#define HH 352
#define WW 352
#define NB 8
#define BX 32
#define BY 16
#define RR 5
#define TW (BX + 2 * RR)   // 42
#define TH (BY + 2 * RR)   // 26
#define NTHREADS (BX * BY) // 512

__device__ float g_num;
__device__ float g_den;

__global__ void init_kernel() {
    g_num = 0.0f;
    g_den = 0.0f;
}

__global__ __launch_bounds__(NTHREADS) void loss_kernel(
    const float* __restrict__ pred,
    const float* __restrict__ feat)
{
    __shared__ float4 tile[TH][TW];

    const int n  = blockIdx.z;
    const int x0 = blockIdx.x * BX;
    const int y0 = blockIdx.y * BY;
    const int tx = threadIdx.x;
    const int ty = threadIdx.y;
    const int tid = ty * BX + tx;

    const float* pr = pred + (size_t)n * (HH * WW);
    const float* fr = feat + (size_t)n * (3 * HH * WW);

    // Cooperative load of (BY+10) x (BX+10) halo tile, packed (r,g,b,sal).
    // Zero padding outside the image (matches jnp.pad on features).
    for (int i = tid; i < TH * TW; i += NTHREADS) {
        int yy = i / TW;
        int xx = i - yy * TW;
        int gy = y0 + yy - RR;
        int gx = x0 + xx - RR;
        float4 v = make_float4(0.f, 0.f, 0.f, 0.f);
        if (gy >= 0 && gy < HH && gx >= 0 && gx < WW) {
            int idx = gy * WW + gx;
            v.x = fr[idx];
            v.y = fr[HH * WW + idx];
            v.z = fr[2 * HH * WW + idx];
            v.w = pr[idx];
        }
        tile[yy][xx] = v;
    }
    __syncthreads();

    const float4 c = tile[ty + RR][tx + RR];

    // 11x11 bilateral-weighted |d_sal| accumulation
    float loss = 0.0f;
    #pragma unroll 1
    for (int dy = 0; dy < 2 * RR + 1; ++dy) {
        #pragma unroll
        for (int dx = 0; dx < 2 * RR + 1; ++dx) {
            float4 w = tile[ty + dy][tx + dx];
            float dr = w.x - c.x;
            float dg = w.y - c.y;
            float db = w.z - c.z;
            float s  = dr * dr + dg * dg + db * db;
            float wgt = __expf(-200.0f * s);
            loss += wgt * fabsf(w.w - c.w);
        }
    }

    // Edge mask: dil (5x5 max of lbl over VALID pixels) - ero (5x5 min over VALID).
    // OOB contributes nothing to max (shared pad is 0 -> lbl 0, never raises max);
    // for the min (ero) OOB must be ignored -> treat OOB as true.
    const int gy = y0 + ty;
    const int gx = x0 + tx;
    bool anyv = false;
    bool allv = true;
    #pragma unroll
    for (int dy = -2; dy <= 2; ++dy) {
        #pragma unroll
        for (int dx = -2; dx <= 2; ++dx) {
            int yy = gy + dy;
            int xx = gx + dx;
            bool inb = (yy >= 0) && (yy < HH) && (xx >= 0) && (xx < WW);
            bool l = tile[ty + RR + dy][tx + RR + dx].w > 0.5f;
            anyv = anyv || (inb && l);
            allv = allv && ((!inb) || l);
        }
    }
    float m = (anyv ? 1.0f : 0.0f) - (allv ? 1.0f : 0.0f);
    float num = (m != 0.0f) ? loss : 0.0f;

    // Block reduction: warp shuffle + shared partials + 2 atomics per block.
    #pragma unroll
    for (int o = 16; o > 0; o >>= 1) {
        num += __shfl_xor_sync(0xffffffffu, num, o);
        m   += __shfl_xor_sync(0xffffffffu, m, o);
    }
    __shared__ float s_num[NTHREADS / 32];
    __shared__ float s_den[NTHREADS / 32];
    const int wid = tid >> 5;
    const int lid = tid & 31;
    if (lid == 0) {
        s_num[wid] = num;
        s_den[wid] = m;
    }
    __syncthreads();
    if (wid == 0) {
        float a = (lid < NTHREADS / 32) ? s_num[lid] : 0.0f;
        float b = (lid < NTHREADS / 32) ? s_den[lid] : 0.0f;
        #pragma unroll
        for (int o = 8; o > 0; o >>= 1) {
            a += __shfl_xor_sync(0xffffffffu, a, o);
            b += __shfl_xor_sync(0xffffffffu, b, o);
        }
        if (lid == 0) {
            atomicAdd(&g_num, a);
            atomicAdd(&g_den, b);
        }
    }
}

__global__ void final_kernel(float* __restrict__ out) {
    out[0] = g_num / (g_den + 1e-6f);
}

extern "C" void kernel_launch(void* const* d_in, const int* in_sizes, int n_in,
                              void* d_out, int out_size) {
    const float* pred = (const float*)d_in[0]; // (8,1,352,352)
    const float* feat = (const float*)d_in[1]; // (8,3,352,352)
    float* out = (float*)d_out;                // scalar

    init_kernel<<<1, 1>>>();
    dim3 grid(WW / BX, HH / BY, NB); // (11, 22, 8) -- exact tiling, 352 = 32*11 = 16*22
    dim3 block(BX, BY, 1);
    loss_kernel<<<grid, block>>>(pred, feat);
    final_kernel<<<1, 1>>>(out);
}

// round 2
// speedup vs baseline: 1.3303x; 1.3303x over previous
#include <cuda_runtime.h>

#define HH 352
#define WW 352
#define NB 8

#define TILE 32                 // 32x32 pixel tile per block
#define RR 5
#define HALO_W (TILE + 2*RR)    // 42 sites in x
#define PAIRROWS (TILE/2 + 2*RR)// 26 pair-rows (each holds rows y and y+16)
#define ROWB 1536               // padded bytes per pair-row (42 sites swizzled < 1536)
#define NTHREADS 128            // 8 threads x (4 px each) * 16 threads y

typedef unsigned long long u64;
union F2U { float2 f; u64 u; };

__device__ __forceinline__ u64 pk2(float lo, float hi){ F2U t; t.f.x=lo; t.f.y=hi; return t.u; }
__device__ __forceinline__ float2 up2(u64 v){ F2U t; t.u=v; return t.f; }
__device__ __forceinline__ u64 fma2(u64 a,u64 b,u64 c){ u64 d; asm("fma.rn.f32x2 %0,%1,%2,%3;":"=l"(d):"l"(a),"l"(b),"l"(c)); return d; }
__device__ __forceinline__ u64 mul2(u64 a,u64 b){ u64 d; asm("mul.rn.f32x2 %0,%1,%2;":"=l"(d):"l"(a),"l"(b)); return d; }
__device__ __forceinline__ u64 add2(u64 a,u64 b){ u64 d; asm("add.rn.f32x2 %0,%1,%2;":"=l"(d):"l"(a),"l"(b)); return d; }
__device__ __forceinline__ float ex2f(float x){ float r; asm("ex2.approx.ftz.f32 %0,%1;":"=f"(r):"f"(x)); return r; }

__device__ float g_num;
__device__ float g_den;

__global__ void init_kernel() { g_num = 0.0f; g_den = 0.0f; }

// swizzled byte offset of site x within a pair-row (x in 0..41), 32B/site + 16B pad per 4 sites
__device__ __forceinline__ int soffx(int x){ return (x<<5) + ((x>>2)<<4); }

__global__ __launch_bounds__(NTHREADS) void loss_kernel(
    const float* __restrict__ pred,
    const float* __restrict__ feat)
{
    __shared__ unsigned char smem[PAIRROWS * ROWB];

    const int n  = blockIdx.z;
    const int x0 = blockIdx.x * TILE;
    const int y0 = blockIdx.y * TILE;
    const int tid = threadIdx.x;
    const int txb = (tid & 7) * 4;   // first of 4 consecutive x pixels
    const int p0  = tid >> 3;        // pair row 0..15 (rows y0+p0 and y0+16+p0)

    const float* pr = pred + (size_t)n * (HH * WW);
    const float* fr = feat + (size_t)n * (3 * HH * WW);

    // ---- Fill halo tile: site (p, x) holds pixels (y0+p-5, x0+x-5) [lo] and +16 rows [hi],
    //      channels packed as pairs: chunkA={r_lo,r_hi,g_lo,g_hi}, chunkB={b_lo,b_hi,s_lo,s_hi}
    for (int i = tid; i < PAIRROWS * HALO_W; i += NTHREADS) {
        int p = i / HALO_W;
        int x = i - p * HALO_W;
        int gyL = y0 + p - RR;
        int gyH = gyL + 16;
        int gx  = x0 + x - RR;
        float rl=0.f,gl=0.f,bl=0.f,sl=0.f, rh=0.f,gh=0.f,bh=0.f,sh=0.f;
        bool inx = ((unsigned)gx < WW);
        if (inx && (unsigned)gyL < HH) {
            int idx = gyL * WW + gx;
            rl = fr[idx]; gl = fr[HH*WW + idx]; bl = fr[2*HH*WW + idx]; sl = pr[idx];
        }
        if (inx && (unsigned)gyH < HH) {
            int idx = gyH * WW + gx;
            rh = fr[idx]; gh = fr[HH*WW + idx]; bh = fr[2*HH*WW + idx]; sh = pr[idx];
        }
        unsigned char* dst = smem + p * ROWB + soffx(x);
        *(float4*)(dst)      = make_float4(rl, rh, gl, gh);
        *(float4*)(dst + 16) = make_float4(bl, bh, sl, sh);
    }
    __syncthreads();

    const float KC = 16.98643601465f;          // sqrt(200 * log2(e))
    const u64 K2 = pk2(KC, KC);
    const u64 M1 = pk2(-1.0f, -1.0f);

    // ---- Centers (4 pixels in x, each a lo/hi pair)
    u64 crK[4], cgK[4], cbK[4], csn[4];
    #pragma unroll
    for (int j = 0; j < 4; ++j) {
        const unsigned char* cp = smem + (p0 + RR) * ROWB + soffx(txb + RR + j);
        ulonglong2 A = *(const ulonglong2*)cp;
        ulonglong2 B = *(const ulonglong2*)(cp + 16);
        float2 r2 = up2(A.x), g2 = up2(A.y), b2 = up2(B.x), s2 = up2(B.y);
        crK[j] = pk2(-KC*r2.x, -KC*r2.y);
        cgK[j] = pk2(-KC*g2.x, -KC*g2.y);
        cbK[j] = pk2(-KC*b2.x, -KC*b2.y);
        csn[j] = pk2(-s2.x, -s2.y);
    }

    u64 loss2[4] = {0ull, 0ull, 0ull, 0ull};

    // ---- 11x11 bilateral accumulation; dy rolled, 14-site sliding pass unrolled
    #pragma unroll 1
    for (int dy = 0; dy < 2*RR + 1; ++dy) {
        const unsigned char* rb = smem + (p0 + dy) * ROWB + txb * 36; // 36 = 32 + 16/4
        #pragma unroll
        for (int s = 0; s < 14; ++s) {
            const unsigned char* sp = rb + s*32 + (s>>2)*16;
            ulonglong2 A = *(const ulonglong2*)sp;
            ulonglong2 B = *(const ulonglong2*)(sp + 16);
            u64 wr = A.x, wg = A.y, wb = B.x, ws = B.y;
            #pragma unroll
            for (int j = 0; j < 4; ++j) {
                int dx = s - j;
                if (dx < 0 || dx > 10) continue;
                u64 dr = fma2(wr, K2, crK[j]);
                u64 dg = fma2(wg, K2, cgK[j]);
                u64 db = fma2(wb, K2, cbK[j]);
                u64 ss = mul2(dr, dr);
                ss = fma2(dg, dg, ss);
                ss = fma2(db, db, ss);
                u64 t = mul2(ss, M1);
                float2 tf = up2(t);
                u64 w2 = pk2(ex2f(tf.x), ex2f(tf.y));
                u64 d  = add2(ws, csn[j]) & 0x7FFFFFFF7FFFFFFFull;
                loss2[j] = fma2(w2, d, loss2[j]);
            }
        }
    }

    // ---- Edge mask (5x5 dilate/erode over valid pixels) + masked accumulation
    float num = 0.0f, den = 0.0f;
    #pragma unroll 1
    for (int j = 0; j < 4; ++j) {
        bool anyL = false, allL = true, anyH = false, allH = true;
        #pragma unroll
        for (int dy2 = -2; dy2 <= 2; ++dy2) {
            #pragma unroll
            for (int dx2 = -2; dx2 <= 2; ++dx2) {
                int hp = p0 + RR + dy2;
                int hx = txb + RR + j + dx2;
                u64 spair = *(const u64*)(smem + hp * ROWB + soffx(hx) + 24);
                float2 sv = up2(spair);
                int gyL = y0 + p0 + dy2;
                int gyH = gyL + 16;
                int gx  = x0 + txb + j + dx2;
                bool inx  = ((unsigned)gx < WW);
                bool inbL = inx && ((unsigned)gyL < HH);
                bool inbH = inx && ((unsigned)gyH < HH);
                bool lL = sv.x > 0.5f;
                bool lH = sv.y > 0.5f;
                anyL = anyL || (inbL && lL);
                allL = allL && (!inbL || lL);
                anyH = anyH || (inbH && lH);
                allH = allH && (!inbH || lH);
            }
        }
        float mL = (anyL ? 1.0f : 0.0f) - (allL ? 1.0f : 0.0f);
        float mH = (anyH ? 1.0f : 0.0f) - (allH ? 1.0f : 0.0f);
        float2 lj = up2(loss2[j]);
        num += (mL != 0.0f ? lj.x : 0.0f) + (mH != 0.0f ? lj.y : 0.0f);
        den += mL + mH;
    }

    // ---- Block reduction + atomics
    #pragma unroll
    for (int o = 16; o > 0; o >>= 1) {
        num += __shfl_xor_sync(0xffffffffu, num, o);
        den += __shfl_xor_sync(0xffffffffu, den, o);
    }
    __shared__ float s_num[NTHREADS/32];
    __shared__ float s_den[NTHREADS/32];
    const int wid = tid >> 5;
    const int lid = tid & 31;
    if (lid == 0) { s_num[wid] = num; s_den[wid] = den; }
    __syncthreads();
    if (wid == 0) {
        float a = (lid < NTHREADS/32) ? s_num[lid] : 0.0f;
        float b = (lid < NTHREADS/32) ? s_den[lid] : 0.0f;
        #pragma unroll
        for (int o = 2; o > 0; o >>= 1) {
            a += __shfl_xor_sync(0xffffffffu, a, o);
            b += __shfl_xor_sync(0xffffffffu, b, o);
        }
        if (lid == 0) { atomicAdd(&g_num, a); atomicAdd(&g_den, b); }
    }
}

__global__ void final_kernel(float* __restrict__ out) {
    out[0] = g_num / (g_den + 1e-6f);
}

extern "C" void kernel_launch(void* const* d_in, const int* in_sizes, int n_in,
                              void* d_out, int out_size) {
    const float* pred = (const float*)d_in[0]; // (8,1,352,352)
    const float* feat = (const float*)d_in[1]; // (8,3,352,352)
    float* out = (float*)d_out;

    init_kernel<<<1, 1>>>();
    dim3 grid(WW / TILE, HH / TILE, NB); // (11, 11, 8)
    loss_kernel<<<grid, NTHREADS>>>(pred, feat);
    final_kernel<<<1, 1>>>(out);
}